// round 11
// baseline (speedup 1.0000x reference)
#include <cuda_runtime.h>
#include <cuda_fp16.h>
#include <cstdint>

// Conv2D 3x3 s1 p1 -> FUSED implicit GEMM, mma.sync fp16 m16n8k16, single
// term D = fp16(W)*fp16(x). R11: no materialized im2col -- the B tile is
// gathered in-kernel from fp32 x (L2-resident, 51MB) with register staging
// one chunk ahead (R3-proven skeleton), 2 CTAs/SM. Only weights are prepped.

namespace {
constexpr int IN_C = 128, OUT_C = 256, H = 56, W = 56, BATCH = 32;
constexpr int HW   = H * W;            // 3136
constexpr int Ndim = BATCH * HW;       // 100352
constexpr int Kdim = IN_C * 9;         // 1152

constexpr int BM = 128, BK = 32;
constexpr int NCH  = Kdim / BK;        // 36 chunks; chunk c: tap r=c>>2, icb=(c&3)*32
constexpr int MBLK = OUT_C / BM;       // 2
constexpr int NT   = Ndim / 128;       // 784

constexpr int A_CH = BM * 80;          // [128 m][32 k] fp16, 80B padded rows = 10240
constexpr int B_CH = BK * 272;         // [32 k][128 n] fp16, 272B padded rows = 8704
constexpr int STAGE  = A_CH + B_CH;    // 18944
constexpr int OFF_A  = 0;
constexpr int OFF_B  = A_CH;
constexpr int SMEM_TOTAL = 2 * STAGE;  // 37888 -> 2 CTAs/SM easily
}  // namespace

// device scratch (allocation-free rule): prepped fp16 weight images only
__device__ __align__(16) unsigned char g_A[(size_t)MBLK * NCH * A_CH];   // 0.7MB

// ---------------- helpers ----------------
__device__ __forceinline__ uint32_t smem_u32(const void* p) {
    uint32_t a;
    asm("{ .reg .u64 t; cvta.to.shared.u64 t, %1; cvt.u32.u64 %0, t; }" : "=r"(a) : "l"(p));
    return a;
}
__device__ __forceinline__ void ldsm4(uint32_t r[4], uint32_t addr) {
    asm volatile("ldmatrix.sync.aligned.m8n8.x4.shared.b16 {%0,%1,%2,%3}, [%4];"
                 : "=r"(r[0]), "=r"(r[1]), "=r"(r[2]), "=r"(r[3]) : "r"(addr));
}
__device__ __forceinline__ void ldsm4t(uint32_t* r, uint32_t addr) {
    asm volatile("ldmatrix.sync.aligned.m8n8.x4.trans.shared.b16 {%0,%1,%2,%3}, [%4];"
                 : "=r"(r[0]), "=r"(r[1]), "=r"(r[2]), "=r"(r[3]) : "r"(addr));
}
__device__ __forceinline__ void mma_fp16(float acc[4], const uint32_t a[4],
                                         uint32_t b0, uint32_t b1) {
    asm volatile(
        "mma.sync.aligned.m16n8k16.row.col.f32.f16.f16.f32 "
        "{%0,%1,%2,%3}, {%4,%5,%6,%7}, {%8,%9}, {%0,%1,%2,%3};"
        : "+f"(acc[0]), "+f"(acc[1]), "+f"(acc[2]), "+f"(acc[3])
        : "r"(a[0]), "r"(a[1]), "r"(a[2]), "r"(a[3]), "r"(b0), "r"(b1));
}
__device__ __forceinline__ uint32_t pack2h(__half a, __half b) {
    __half2 t(a, b);
    return *reinterpret_cast<uint32_t*>(&t);
}

// ---------------- prep: weights -> k-reordered SMEM-image fp16 -------------
__global__ void prep_weights(const float* __restrict__ Wk) {
    const int c = blockIdx.x;                      // 36 chunks
    const int m = threadIdx.x;                     // 256 = OUT_C
    const int r  = c >> 2;
    const int icb = (c & 3) * 32;

    const float* src = Wk + (size_t)m * Kdim + r;  // orig k = ic*9 + r
    size_t base = ((size_t)(m >> 7) * NCH + c) * A_CH + (size_t)(m & 127) * 80;
    #pragma unroll
    for (int kkg = 0; kkg < 4; ++kkg) {
        uint32_t hv[4];
        #pragma unroll
        for (int p = 0; p < 4; ++p) {
            int ic0 = icb + kkg * 8 + 2 * p;
            hv[p] = pack2h(__float2half(src[ic0 * 9]),
                           __float2half(src[(ic0 + 1) * 9]));
        }
        *reinterpret_cast<uint4*>(g_A + base + kkg * 16) =
            make_uint4(hv[0], hv[1], hv[2], hv[3]);
    }
}

// ---------------- fused GEMM: in-kernel im2col gather + HMMA ---------------
__global__ __launch_bounds__(256, 2)
void conv_fused(const float* __restrict__ x, const float* __restrict__ bias,
                float* __restrict__ out)
{
    extern __shared__ char smem[];
    const uint32_t sb = smem_u32(smem);
    const int tid = threadIdx.x, lane = tid & 31, wp = tid >> 5;
    const int warp_m = wp >> 2, warp_n = wp & 3;
    const int mblk = blockIdx.x, t = blockIdx.y;   // mblk fastest

    // ---- fixed gather geometry (2 units/thread: rows r0 and r0+16, group g) ----
    const int r0 = tid >> 4;           // B row 0..15 (unit 0); +16 for unit 1
    const int g  = tid & 15;           // 8-wide n group (56%8==0: never crosses h)
    const int n0  = t * 128 + g * 8;
    const int ni  = n0 / HW;
    const int hw0 = n0 - ni * HW;
    const int oh  = hw0 / W;
    const int ow0 = hw0 - oh * W;
    const float* xb = x + (size_t)ni * IN_C * HW;

    const unsigned char* gA = g_A + (size_t)mblk * NCH * A_CH;

    // ---- staging registers ----
    float  bpre[2][8];
    uint2  apre[5];

    auto ldg_chunk = [&](int c) {
        // A: 1280 uint2, 5 per thread
        const uint2* asrc = reinterpret_cast<const uint2*>(gA + (size_t)c * A_CH);
        #pragma unroll
        for (int k = 0; k < 5; ++k) apre[k] = __ldg(asrc + tid + k * 256);
        // B: im2col gather from fp32 x
        const int r  = c >> 2;
        const int kh = r / 3, kw = r - kh * 3;
        const int icb = (c & 3) * 32;
        const int ih  = oh + kh - 1;
        const bool rv = (unsigned)ih < (unsigned)H;
        const int iw0 = ow0 + kw - 1;
        #pragma unroll
        for (int u = 0; u < 2; ++u) {
            const int ic = icb + r0 + u * 16;
            const float* src = xb + ((size_t)ic * H + ih) * W;
            #pragma unroll
            for (int p = 0; p < 8; ++p) {
                int iw = iw0 + p;
                bpre[u][p] = (rv && (unsigned)iw < (unsigned)W) ? __ldg(src + iw) : 0.f;
            }
        }
    };

    auto sts_chunk = [&](int buf) {
        const uint32_t st = sb + buf * STAGE;
        #pragma unroll
        for (int k = 0; k < 5; ++k)
            *reinterpret_cast<uint2*>(smem + buf * STAGE + OFF_A + (tid + k * 256) * 8) = apre[k];
        #pragma unroll
        for (int u = 0; u < 2; ++u) {
            uint4 v = make_uint4(
                pack2h(__float2half(bpre[u][0]), __float2half(bpre[u][1])),
                pack2h(__float2half(bpre[u][2]), __float2half(bpre[u][3])),
                pack2h(__float2half(bpre[u][4]), __float2half(bpre[u][5])),
                pack2h(__float2half(bpre[u][6]), __float2half(bpre[u][7])));
            *reinterpret_cast<uint4*>(smem + buf * STAGE + OFF_B + (r0 + u * 16) * 272 + g * 16) = v;
        }
        (void)st;
    };

    float acc[4][4][4];
    #pragma unroll
    for (int a = 0; a < 4; ++a)
        #pragma unroll
        for (int b = 0; b < 4; ++b)
            #pragma unroll
            for (int cc = 0; cc < 4; ++cc) acc[a][b][cc] = 0.f;

    const uint32_t a_lane = (warp_m * 64 + (lane & 15)) * 80 + (lane >> 4) * 16;
    const uint32_t b_lane = (lane & 15) * 272 + warp_n * 64 + (lane >> 4) * 16;

    auto compute = [&](int buf) {
        const uint32_t ab = sb + buf * STAGE + OFF_A + a_lane;
        const uint32_t bb = sb + buf * STAGE + OFF_B + b_lane;
        #pragma unroll
        for (int ks = 0; ks < 2; ++ks) {
            uint32_t Bv[2][4];
            #pragma unroll
            for (int jh = 0; jh < 2; ++jh)
                ldsm4t(Bv[jh], bb + ks * 4352 + jh * 32);
            #pragma unroll
            for (int mt = 0; mt < 4; ++mt) {
                uint32_t Av[4];
                ldsm4(Av, ab + mt * 1280 + ks * 32);
                #pragma unroll
                for (int nt = 0; nt < 4; ++nt) {
                    uint32_t b0 = Bv[nt >> 1][(nt & 1) * 2];
                    uint32_t b1 = Bv[nt >> 1][(nt & 1) * 2 + 1];
                    mma_fp16(acc[mt][nt], Av, b0, b1);
                }
            }
        }
    };

    // ---- mainloop: double-buffered, register-staged (R3-proven skeleton) ----
    ldg_chunk(0);
    sts_chunk(0);
    __syncthreads();
    for (int c = 0; c < NCH; ++c) {
        if (c + 1 < NCH) ldg_chunk(c + 1);
        compute(c & 1);
        if (c + 1 < NCH) sts_chunk((c + 1) & 1);
        __syncthreads();
    }

    // ---- epilogue: bias + direct stores (layout proven since R3) ----
    #pragma unroll
    for (int mt = 0; mt < 4; ++mt) {
        int oc0 = mblk * BM + warp_m * 64 + mt * 16 + (lane >> 2);
        float b0 = bias[oc0], b1 = bias[oc0 + 8];
        #pragma unroll
        for (int nt = 0; nt < 4; ++nt) {
            int gg = t * 128 + warp_n * 32 + nt * 8 + (lane & 3) * 2;
            int nim = gg / HW;
            int hw  = gg - nim * HW;
            float2 v0 = make_float2(acc[mt][nt][0] + b0, acc[mt][nt][1] + b0);
            float2 v1 = make_float2(acc[mt][nt][2] + b1, acc[mt][nt][3] + b1);
            *reinterpret_cast<float2*>(out + ((size_t)nim * OUT_C + oc0) * HW + hw)     = v0;
            *reinterpret_cast<float2*>(out + ((size_t)nim * OUT_C + oc0 + 8) * HW + hw) = v1;
        }
    }
}

// ---------------- launch ----------------
extern "C" void kernel_launch(void* const* d_in, const int* in_sizes, int n_in,
                              void* d_out, int out_size) {
    const float* x    = (const float*)d_in[0];
    const float* Wk   = (const float*)d_in[1];
    const float* bias = (const float*)d_in[2];
    float* out        = (float*)d_out;

    cudaFuncSetAttribute(conv_fused, cudaFuncAttributeMaxDynamicSharedMemorySize, SMEM_TOTAL);

    prep_weights<<<NCH, 256>>>(Wk);
    conv_fused<<<dim3(MBLK, NT), 256, SMEM_TOTAL>>>(x, bias, out);
}

// round 12
// speedup vs baseline: 1.5608x; 1.5608x over previous
#include <cuda_runtime.h>
#include <cuda_fp16.h>
#include <cstdint>

// Conv2D 3x3 s1 p1 -> FUSED implicit GEMM, mma.sync fp16 m16n8k16, single
// term D = fp16(W)*fp16(x). R12 = R11 fusion with the gather fixed:
// x is pre-converted to fp16 (g_xh, L2-resident); every 8-wide output group
// is 16B-aligned in x_fp16, so a tap window = 1-2 LDG.128 + funnel-shift
// (vs R11's 8 scalar LDG.32 + cvts that pinned L1 at 84%).

namespace {
constexpr int IN_C = 128, OUT_C = 256, H = 56, W = 56, BATCH = 32;
constexpr int HW   = H * W;            // 3136
constexpr int Ndim = BATCH * HW;       // 100352
constexpr int Kdim = IN_C * 9;         // 1152

constexpr int BM = 128, BK = 32;
constexpr int NCH  = Kdim / BK;        // 36 chunks; chunk c: tap r=c>>2, icb=(c&3)*32
constexpr int MBLK = OUT_C / BM;       // 2
constexpr int NT   = Ndim / 128;       // 784

constexpr int A_CH = BM * 80;          // [128 m][32 k] fp16, 80B padded rows = 10240
constexpr int B_CH = BK * 272;         // [32 k][128 n] fp16, 272B padded rows = 8704
constexpr int STAGE  = A_CH + B_CH;    // 18944
constexpr int OFF_A  = 0;
constexpr int OFF_B  = A_CH;
constexpr int SMEM_TOTAL = 2 * STAGE;  // 37888

constexpr int XCONV_BLOCKS = (int)((size_t)Ndim * IN_C / 8 / 256);  // 6272
}  // namespace

// device scratch (allocation-free rule)
__device__ __align__(16) unsigned char g_A[(size_t)MBLK * NCH * A_CH];  // 0.7MB
__device__ __align__(16) __half g_xh[(size_t)Ndim * IN_C];              // 25.7MB

// ---------------- helpers ----------------
__device__ __forceinline__ uint32_t smem_u32(const void* p) {
    uint32_t a;
    asm("{ .reg .u64 t; cvta.to.shared.u64 t, %1; cvt.u32.u64 %0, t; }" : "=r"(a) : "l"(p));
    return a;
}
__device__ __forceinline__ void ldsm4(uint32_t r[4], uint32_t addr) {
    asm volatile("ldmatrix.sync.aligned.m8n8.x4.shared.b16 {%0,%1,%2,%3}, [%4];"
                 : "=r"(r[0]), "=r"(r[1]), "=r"(r[2]), "=r"(r[3]) : "r"(addr));
}
__device__ __forceinline__ void ldsm4t(uint32_t* r, uint32_t addr) {
    asm volatile("ldmatrix.sync.aligned.m8n8.x4.trans.shared.b16 {%0,%1,%2,%3}, [%4];"
                 : "=r"(r[0]), "=r"(r[1]), "=r"(r[2]), "=r"(r[3]) : "r"(addr));
}
__device__ __forceinline__ void mma_fp16(float acc[4], const uint32_t a[4],
                                         uint32_t b0, uint32_t b1) {
    asm volatile(
        "mma.sync.aligned.m16n8k16.row.col.f32.f16.f16.f32 "
        "{%0,%1,%2,%3}, {%4,%5,%6,%7}, {%8,%9}, {%0,%1,%2,%3};"
        : "+f"(acc[0]), "+f"(acc[1]), "+f"(acc[2]), "+f"(acc[3])
        : "r"(a[0]), "r"(a[1]), "r"(a[2]), "r"(a[3]), "r"(b0), "r"(b1));
}
__device__ __forceinline__ uint32_t pack2h(__half a, __half b) {
    __half2 t(a, b);
    return *reinterpret_cast<uint32_t*>(&t);
}

// ---------------- prep: x->fp16 copy (most blocks) + weight images ---------
__global__ __launch_bounds__(256)
void prep_all(const float* __restrict__ x, const float* __restrict__ Wk) {
    if (blockIdx.x < XCONV_BLOCKS) {
        // ---- x -> fp16, 8 elems/thread ----
        const size_t i = (size_t)blockIdx.x * 256 + threadIdx.x;
        const float4* s = reinterpret_cast<const float4*>(x) + i * 2;
        float4 v0 = __ldg(s), v1 = __ldg(s + 1);
        uint4 o = make_uint4(
            pack2h(__float2half(v0.x), __float2half(v0.y)),
            pack2h(__float2half(v0.z), __float2half(v0.w)),
            pack2h(__float2half(v1.x), __float2half(v1.y)),
            pack2h(__float2half(v1.z), __float2half(v1.w)));
        reinterpret_cast<uint4*>(g_xh)[i] = o;
        return;
    }
    // ---- weights -> k-reordered SMEM-image fp16 ----
    const int c = blockIdx.x - XCONV_BLOCKS;       // 36 chunks
    const int m = threadIdx.x;                     // 256 = OUT_C
    const int r  = c >> 2;
    const int icb = (c & 3) * 32;

    const float* src = Wk + (size_t)m * Kdim + r;  // orig k = ic*9 + r
    size_t base = ((size_t)(m >> 7) * NCH + c) * A_CH + (size_t)(m & 127) * 80;
    #pragma unroll
    for (int kkg = 0; kkg < 4; ++kkg) {
        uint32_t hv[4];
        #pragma unroll
        for (int p = 0; p < 4; ++p) {
            int ic0 = icb + kkg * 8 + 2 * p;
            hv[p] = pack2h(__float2half(src[ic0 * 9]),
                           __float2half(src[(ic0 + 1) * 9]));
        }
        *reinterpret_cast<uint4*>(g_A + base + kkg * 16) =
            make_uint4(hv[0], hv[1], hv[2], hv[3]);
    }
}

// ---------------- fused GEMM: vectorized fp16 gather + HMMA ----------------
__global__ __launch_bounds__(256, 2)
void conv_fused2(const float* __restrict__ bias, float* __restrict__ out)
{
    extern __shared__ char smem[];
    const uint32_t sb = smem_u32(smem);
    const int tid = threadIdx.x, lane = tid & 31, wp = tid >> 5;
    const int warp_m = wp >> 2, warp_n = wp & 3;
    const int mblk = blockIdx.x, t = blockIdx.y;   // mblk fastest

    // ---- fixed gather geometry: thread = n-group g (8 cols), rows r0,r0+16 ----
    const int r0 = tid >> 4;
    const int g  = tid & 15;
    const int n0  = t * 128 + g * 8;
    const int ni  = n0 / HW;
    const int hw0 = n0 - ni * HW;
    const int oh  = hw0 / W;
    const int ow0 = hw0 - oh * W;                  // multiple of 8
    const __half* xb = g_xh + (size_t)ni * IN_C * HW;
    const bool hasA = (ow0 > 0);                   // left neighbor group exists
    const bool hasC = (ow0 + 8 < W);               // right neighbor in-bounds

    const unsigned char* gA = g_A + (size_t)mblk * NCH * A_CH;

    uint2 apre[5];
    uint4 bpre[2];

    auto ldg_chunk = [&](int c) {
        const uint2* asrc = reinterpret_cast<const uint2*>(gA + (size_t)c * A_CH);
        #pragma unroll
        for (int k = 0; k < 5; ++k) apre[k] = __ldg(asrc + tid + k * 256);

        const int r  = c >> 2;
        const int kh = r / 3, kw = r - kh * 3;
        const int icb = (c & 3) * 32;
        const int ih  = oh + kh - 1;
        const bool rv = (unsigned)ih < (unsigned)H;
        const uint4 z = make_uint4(0, 0, 0, 0);

        #pragma unroll
        for (int u = 0; u < 2; ++u) {
            const int ic = icb + r0 + u * 16;
            const uint4* p = reinterpret_cast<const uint4*>(
                xb + ((size_t)ic * H + ih) * W + ow0);
            uint4 B8 = rv ? __ldg(p) : z;
            uint4 res;
            if (kw == 1) {
                res = B8;
            } else if (kw == 0) {                  // window = [A7, B0..B6]
                uint4 A8 = (rv && hasA) ? __ldg(p - 1) : z;
                res.x = __funnelshift_r(A8.w, B8.x, 16);
                res.y = __funnelshift_r(B8.x, B8.y, 16);
                res.z = __funnelshift_r(B8.y, B8.z, 16);
                res.w = __funnelshift_r(B8.z, B8.w, 16);
            } else {                               // kw==2: window = [B1..B7, C0]
                uint4 C8 = (rv && hasC) ? __ldg(p + 1) : z;
                res.x = __funnelshift_r(B8.x, B8.y, 16);
                res.y = __funnelshift_r(B8.y, B8.z, 16);
                res.z = __funnelshift_r(B8.z, B8.w, 16);
                res.w = __funnelshift_r(B8.w, C8.x, 16);
            }
            bpre[u] = res;
        }
    };

    auto sts_chunk = [&](int buf) {
        #pragma unroll
        for (int k = 0; k < 5; ++k)
            *reinterpret_cast<uint2*>(smem + buf * STAGE + OFF_A + (tid + k * 256) * 8) = apre[k];
        #pragma unroll
        for (int u = 0; u < 2; ++u)
            *reinterpret_cast<uint4*>(smem + buf * STAGE + OFF_B + (r0 + u * 16) * 272 + g * 16) = bpre[u];
    };

    float acc[4][4][4];
    #pragma unroll
    for (int a = 0; a < 4; ++a)
        #pragma unroll
        for (int b = 0; b < 4; ++b)
            #pragma unroll
            for (int cc = 0; cc < 4; ++cc) acc[a][b][cc] = 0.f;

    const uint32_t a_lane = (warp_m * 64 + (lane & 15)) * 80 + (lane >> 4) * 16;
    const uint32_t b_lane = (lane & 15) * 272 + warp_n * 64 + (lane >> 4) * 16;

    auto compute = [&](int buf) {
        const uint32_t ab = sb + buf * STAGE + OFF_A + a_lane;
        const uint32_t bb = sb + buf * STAGE + OFF_B + b_lane;
        #pragma unroll
        for (int ks = 0; ks < 2; ++ks) {
            uint32_t Bv[2][4];
            #pragma unroll
            for (int jh = 0; jh < 2; ++jh)
                ldsm4t(Bv[jh], bb + ks * 4352 + jh * 32);
            #pragma unroll
            for (int mt = 0; mt < 4; ++mt) {
                uint32_t Av[4];
                ldsm4(Av, ab + mt * 1280 + ks * 32);
                #pragma unroll
                for (int nt = 0; nt < 4; ++nt) {
                    uint32_t b0 = Bv[nt >> 1][(nt & 1) * 2];
                    uint32_t b1 = Bv[nt >> 1][(nt & 1) * 2 + 1];
                    mma_fp16(acc[mt][nt], Av, b0, b1);
                }
            }
        }
    };

    // ---- mainloop: double-buffered, register-staged ----
    ldg_chunk(0);
    sts_chunk(0);
    __syncthreads();
    for (int c = 0; c < NCH; ++c) {
        if (c + 1 < NCH) ldg_chunk(c + 1);
        compute(c & 1);
        if (c + 1 < NCH) sts_chunk((c + 1) & 1);
        __syncthreads();
    }

    // ---- epilogue: bias + direct stores (layout proven since R3) ----
    #pragma unroll
    for (int mt = 0; mt < 4; ++mt) {
        int oc0 = mblk * BM + warp_m * 64 + mt * 16 + (lane >> 2);
        float b0 = bias[oc0], b1 = bias[oc0 + 8];
        #pragma unroll
        for (int nt = 0; nt < 4; ++nt) {
            int gg = t * 128 + warp_n * 32 + nt * 8 + (lane & 3) * 2;
            int nim = gg / HW;
            int hw  = gg - nim * HW;
            float2 v0 = make_float2(acc[mt][nt][0] + b0, acc[mt][nt][1] + b0);
            float2 v1 = make_float2(acc[mt][nt][2] + b1, acc[mt][nt][3] + b1);
            *reinterpret_cast<float2*>(out + ((size_t)nim * OUT_C + oc0) * HW + hw)     = v0;
            *reinterpret_cast<float2*>(out + ((size_t)nim * OUT_C + oc0 + 8) * HW + hw) = v1;
        }
    }
}

// ---------------- launch ----------------
extern "C" void kernel_launch(void* const* d_in, const int* in_sizes, int n_in,
                              void* d_out, int out_size) {
    const float* x    = (const float*)d_in[0];
    const float* Wk   = (const float*)d_in[1];
    const float* bias = (const float*)d_in[2];
    float* out        = (float*)d_out;

    cudaFuncSetAttribute(conv_fused2, cudaFuncAttributeMaxDynamicSharedMemorySize, SMEM_TOTAL);

    prep_all<<<XCONV_BLOCKS + NCH, 256>>>(x, Wk);
    conv_fused2<<<dim3(MBLK, NT), 256, SMEM_TOTAL>>>(bias, out);
}

// round 13
// speedup vs baseline: 1.6382x; 1.0496x over previous
#include <cuda_runtime.h>
#include <cuda_fp16.h>
#include <cstdint>

// Conv2D 3x3 s1 p1 -> FUSED implicit GEMM, mma.sync fp16 m16n8k16, single
// term D = fp16(W)*fp16(x). R13 = R12 with the A path moved off the LSU:
// weight chunk images travel via cp.async.bulk (bulk/TMA engine, zero LSU
// work, mbarrier-signaled) instead of per-thread LDG+STS (-19% L1 traffic).
// B keeps the R12 vectorized gather (LDG.128 + funnel-shift from fp16 x).

namespace {
constexpr int IN_C = 128, OUT_C = 256, H = 56, W = 56, BATCH = 32;
constexpr int HW   = H * W;            // 3136
constexpr int Ndim = BATCH * HW;       // 100352
constexpr int Kdim = IN_C * 9;         // 1152

constexpr int BM = 128, BK = 32;
constexpr int NCH  = Kdim / BK;        // 36 chunks; chunk c: tap r=c>>2, icb=(c&3)*32
constexpr int MBLK = OUT_C / BM;       // 2
constexpr int NT   = Ndim / 128;       // 784

constexpr int A_CH = BM * 80;          // [128 m][32 k] fp16, 80B padded rows = 10240
constexpr int B_CH = BK * 272;         // [32 k][128 n] fp16, 272B padded rows = 8704
constexpr int STAGE  = A_CH + B_CH;    // 18944 (16B-aligned)
constexpr int OFF_A  = 0;
constexpr int OFF_B  = A_CH;
constexpr int SM_BAR = 2 * STAGE;      // 37888
constexpr int SMEM_TOTAL = SM_BAR + 64;

constexpr int XCONV_BLOCKS = (int)((size_t)Ndim * IN_C / 8 / 256);  // 6272
}  // namespace

// device scratch (allocation-free rule)
__device__ __align__(16) unsigned char g_A[(size_t)MBLK * NCH * A_CH];  // 0.7MB
__device__ __align__(16) __half g_xh[(size_t)Ndim * IN_C];              // 25.7MB

// ---------------- helpers ----------------
__device__ __forceinline__ uint32_t smem_u32(const void* p) {
    uint32_t a;
    asm("{ .reg .u64 t; cvta.to.shared.u64 t, %1; cvt.u32.u64 %0, t; }" : "=r"(a) : "l"(p));
    return a;
}
__device__ __forceinline__ void ldsm4(uint32_t r[4], uint32_t addr) {
    asm volatile("ldmatrix.sync.aligned.m8n8.x4.shared.b16 {%0,%1,%2,%3}, [%4];"
                 : "=r"(r[0]), "=r"(r[1]), "=r"(r[2]), "=r"(r[3]) : "r"(addr));
}
__device__ __forceinline__ void ldsm4t(uint32_t* r, uint32_t addr) {
    asm volatile("ldmatrix.sync.aligned.m8n8.x4.trans.shared.b16 {%0,%1,%2,%3}, [%4];"
                 : "=r"(r[0]), "=r"(r[1]), "=r"(r[2]), "=r"(r[3]) : "r"(addr));
}
__device__ __forceinline__ void mma_fp16(float acc[4], const uint32_t a[4],
                                         uint32_t b0, uint32_t b1) {
    asm volatile(
        "mma.sync.aligned.m16n8k16.row.col.f32.f16.f16.f32 "
        "{%0,%1,%2,%3}, {%4,%5,%6,%7}, {%8,%9}, {%0,%1,%2,%3};"
        : "+f"(acc[0]), "+f"(acc[1]), "+f"(acc[2]), "+f"(acc[3])
        : "r"(a[0]), "r"(a[1]), "r"(a[2]), "r"(a[3]), "r"(b0), "r"(b1));
}
__device__ __forceinline__ uint32_t pack2h(__half a, __half b) {
    __half2 t(a, b);
    return *reinterpret_cast<uint32_t*>(&t);
}
#define MBAR_INIT(a, n)   asm volatile("mbarrier.init.shared.b64 [%0], %1;" :: "r"(a), "r"(n) : "memory")
#define MBAR_EXPECT(a, b) asm volatile("mbarrier.arrive.expect_tx.shared.b64 _, [%0], %1;" :: "r"(a), "r"(b) : "memory")
#define MBAR_INVAL(a)     asm volatile("mbarrier.inval.shared.b64 [%0];" :: "r"(a) : "memory")
__device__ __forceinline__ void mbar_wait(uint32_t mbar, uint32_t parity) {
    asm volatile(
        "{\n\t.reg .pred P;\n"
        "WL_%=:\n\t"
        "mbarrier.try_wait.parity.acquire.cta.shared::cta.b64 P, [%0], %1, 0x989680;\n\t"
        "@P bra.uni WD_%=;\n\t"
        "bra.uni WL_%=;\n"
        "WD_%=:\n\t}"
        :: "r"(mbar), "r"(parity) : "memory");
}
__device__ __forceinline__ void bulk_g2s(uint32_t dst, const void* src, uint32_t bytes, uint32_t mbar) {
    asm volatile(
        "cp.async.bulk.shared::cluster.global.mbarrier::complete_tx::bytes [%0], [%1], %2, [%3];"
        :: "r"(dst), "l"(src), "r"(bytes), "r"(mbar) : "memory");
}

// ---------------- prep: x->fp16 copy (most blocks) + weight images ---------
__global__ __launch_bounds__(256)
void prep_all(const float* __restrict__ x, const float* __restrict__ Wk) {
    if (blockIdx.x < XCONV_BLOCKS) {
        const size_t i = (size_t)blockIdx.x * 256 + threadIdx.x;
        const float4* s = reinterpret_cast<const float4*>(x) + i * 2;
        float4 v0 = __ldg(s), v1 = __ldg(s + 1);
        uint4 o = make_uint4(
            pack2h(__float2half(v0.x), __float2half(v0.y)),
            pack2h(__float2half(v0.z), __float2half(v0.w)),
            pack2h(__float2half(v1.x), __float2half(v1.y)),
            pack2h(__float2half(v1.z), __float2half(v1.w)));
        reinterpret_cast<uint4*>(g_xh)[i] = o;
        return;
    }
    const int c = blockIdx.x - XCONV_BLOCKS;       // 36 chunks
    const int m = threadIdx.x;                     // 256 = OUT_C
    const int r  = c >> 2;
    const int icb = (c & 3) * 32;

    const float* src = Wk + (size_t)m * Kdim + r;  // orig k = ic*9 + r
    size_t base = ((size_t)(m >> 7) * NCH + c) * A_CH + (size_t)(m & 127) * 80;
    #pragma unroll
    for (int kkg = 0; kkg < 4; ++kkg) {
        uint32_t hv[4];
        #pragma unroll
        for (int p = 0; p < 4; ++p) {
            int ic0 = icb + kkg * 8 + 2 * p;
            hv[p] = pack2h(__float2half(src[ic0 * 9]),
                           __float2half(src[(ic0 + 1) * 9]));
        }
        *reinterpret_cast<uint4*>(g_A + base + kkg * 16) =
            make_uint4(hv[0], hv[1], hv[2], hv[3]);
    }
}

// ---------------- fused GEMM: bulk-A + vectorized B gather + HMMA ----------
__global__ __launch_bounds__(256, 2)
void conv_fused3(const float* __restrict__ bias, float* __restrict__ out)
{
    extern __shared__ char smem[];
    const uint32_t sb = smem_u32(smem);
    const int tid = threadIdx.x, lane = tid & 31, wp = tid >> 5;
    const int warp_m = wp >> 2, warp_n = wp & 3;
    const int mblk = blockIdx.x, t = blockIdx.y;   // mblk fastest

    // ---- gather geometry: thread = n-group g (8 cols), rows r0, r0+16 ----
    const int r0 = tid >> 4;
    const int g  = tid & 15;
    const int n0  = t * 128 + g * 8;
    const int ni  = n0 / HW;
    const int hw0 = n0 - ni * HW;
    const int oh  = hw0 / W;
    const int ow0 = hw0 - oh * W;                  // multiple of 8
    const __half* xb = g_xh + (size_t)ni * IN_C * HW;
    const bool hasA = (ow0 > 0);
    const bool hasC = (ow0 + 8 < W);

    const unsigned char* gA = g_A + (size_t)mblk * NCH * A_CH;

    const uint32_t full[2] = {sb + SM_BAR, sb + SM_BAR + 8};
    if (tid == 0) { MBAR_INIT(full[0], 1); MBAR_INIT(full[1], 1); }
    __syncthreads();

    auto loadA = [&](int c, int s) {
        MBAR_EXPECT(full[s], A_CH);
        bulk_g2s(sb + s * STAGE + OFF_A, gA + (size_t)c * A_CH, A_CH, full[s]);
    };
    if (tid == 0) { loadA(0, 0); loadA(1, 1); }

    uint4 bpre[2];
    auto ldgB = [&](int c) {
        const int r  = c >> 2;
        const int kh = r / 3, kw = r - kh * 3;
        const int icb = (c & 3) * 32;
        const int ih  = oh + kh - 1;
        const bool rv = (unsigned)ih < (unsigned)H;
        const uint4 z = make_uint4(0, 0, 0, 0);
        #pragma unroll
        for (int u = 0; u < 2; ++u) {
            const int ic = icb + r0 + u * 16;
            const uint4* p = reinterpret_cast<const uint4*>(
                xb + ((size_t)ic * H + ih) * W + ow0);
            uint4 B8 = rv ? __ldg(p) : z;
            uint4 res;
            if (kw == 1) {
                res = B8;
            } else if (kw == 0) {                  // window = [A7, B0..B6]
                uint4 A8 = (rv && hasA) ? __ldg(p - 1) : z;
                res.x = __funnelshift_r(A8.w, B8.x, 16);
                res.y = __funnelshift_r(B8.x, B8.y, 16);
                res.z = __funnelshift_r(B8.y, B8.z, 16);
                res.w = __funnelshift_r(B8.z, B8.w, 16);
            } else {                               // kw==2: window = [B1..B7, C0]
                uint4 C8 = (rv && hasC) ? __ldg(p + 1) : z;
                res.x = __funnelshift_r(B8.x, B8.y, 16);
                res.y = __funnelshift_r(B8.y, B8.z, 16);
                res.z = __funnelshift_r(B8.z, B8.w, 16);
                res.w = __funnelshift_r(B8.w, C8.x, 16);
            }
            bpre[u] = res;
        }
    };
    auto stsB = [&](int buf) {
        #pragma unroll
        for (int u = 0; u < 2; ++u)
            *reinterpret_cast<uint4*>(smem + buf * STAGE + OFF_B + (r0 + u * 16) * 272 + g * 16) = bpre[u];
    };

    float acc[4][4][4];
    #pragma unroll
    for (int a = 0; a < 4; ++a)
        #pragma unroll
        for (int b = 0; b < 4; ++b)
            #pragma unroll
            for (int cc = 0; cc < 4; ++cc) acc[a][b][cc] = 0.f;

    const uint32_t a_lane = (warp_m * 64 + (lane & 15)) * 80 + (lane >> 4) * 16;
    const uint32_t b_lane = (lane & 15) * 272 + warp_n * 64 + (lane >> 4) * 16;

    auto compute = [&](int buf) {
        const uint32_t ab = sb + buf * STAGE + OFF_A + a_lane;
        const uint32_t bb = sb + buf * STAGE + OFF_B + b_lane;
        #pragma unroll
        for (int ks = 0; ks < 2; ++ks) {
            uint32_t Bv[2][4];
            #pragma unroll
            for (int jh = 0; jh < 2; ++jh)
                ldsm4t(Bv[jh], bb + ks * 4352 + jh * 32);
            #pragma unroll
            for (int mt = 0; mt < 4; ++mt) {
                uint32_t Av[4];
                ldsm4(Av, ab + mt * 1280 + ks * 32);
                #pragma unroll
                for (int nt = 0; nt < 4; ++nt) {
                    uint32_t b0 = Bv[nt >> 1][(nt & 1) * 2];
                    uint32_t b1 = Bv[nt >> 1][(nt & 1) * 2 + 1];
                    mma_fp16(acc[mt][nt], Av, b0, b1);
                }
            }
        }
    };

    // ---- mainloop: B register-staged + syncthreads; A bulk + mbarrier ----
    ldgB(0);
    stsB(0);
    __syncthreads();                               // B0 visible
    int fp[2] = {0, 0};
    for (int c = 0; c < NCH; ++c) {
        const int s = c & 1;
        if (c + 1 < NCH) ldgB(c + 1);
        mbar_wait(full[s], fp[s]); fp[s] ^= 1;     // A chunk c ready
        compute(s);
        if (c + 1 < NCH) stsB((c + 1) & 1);
        __syncthreads();                           // stage s fully consumed
        if (tid == 0 && c + 2 < NCH) loadA(c + 2, s);
    }

    // ---- epilogue: bias + direct stores (layout proven since R3) ----
    #pragma unroll
    for (int mt = 0; mt < 4; ++mt) {
        int oc0 = mblk * BM + warp_m * 64 + mt * 16 + (lane >> 2);
        float b0 = bias[oc0], b1 = bias[oc0 + 8];
        #pragma unroll
        for (int nt = 0; nt < 4; ++nt) {
            int gg = t * 128 + warp_n * 32 + nt * 8 + (lane & 3) * 2;
            int nim = gg / HW;
            int hw  = gg - nim * HW;
            float2 v0 = make_float2(acc[mt][nt][0] + b0, acc[mt][nt][1] + b0);
            float2 v1 = make_float2(acc[mt][nt][2] + b1, acc[mt][nt][3] + b1);
            *reinterpret_cast<float2*>(out + ((size_t)nim * OUT_C + oc0) * HW + hw)     = v0;
            *reinterpret_cast<float2*>(out + ((size_t)nim * OUT_C + oc0 + 8) * HW + hw) = v1;
        }
    }

    __syncthreads();
    if (tid == 0) { MBAR_INVAL(full[0]); MBAR_INVAL(full[1]); }
}

// ---------------- launch ----------------
extern "C" void kernel_launch(void* const* d_in, const int* in_sizes, int n_in,
                              void* d_out, int out_size) {
    const float* x    = (const float*)d_in[0];
    const float* Wk   = (const float*)d_in[1];
    const float* bias = (const float*)d_in[2];
    float* out        = (float*)d_out;

    cudaFuncSetAttribute(conv_fused3, cudaFuncAttributeMaxDynamicSharedMemorySize, SMEM_TOTAL);

    prep_all<<<XCONV_BLOCKS + NCH, 256>>>(x, Wk);
    conv_fused3<<<dim3(MBLK, NT), 256, SMEM_TOTAL>>>(bias, out);
}